// round 3
// baseline (speedup 1.0000x reference)
#include <cuda_runtime.h>
#include <math.h>

#define NN    100000
#define EE    3200000
#define NFEAT 256
#define NHID  128
#define NCLASS 40

// ---------------- scratch (static device globals; no allocation) ----------------
__device__ __align__(16) float g_s1[NN * NHID];     // support1 = x @ W1  (51.2 MB)
__device__ __align__(16) float g_s2[NN * NCLASS];   // s2 = (A@s1 relu'd) @ W2 (16 MB)
__device__ int g_rowptr[NN + 1];

// ---------------- f32x2 packed helpers ----------------
__device__ __forceinline__ unsigned long long ffma2(unsigned long long a,
                                                    unsigned long long b,
                                                    unsigned long long c) {
    unsigned long long d;
    asm("fma.rn.f32x2 %0, %1, %2, %3;" : "=l"(d) : "l"(a), "l"(b), "l"(c));
    return d;
}
__device__ __forceinline__ unsigned long long dup2(float a) {
    unsigned long long d;
    asm("mov.b64 %0, {%1, %1};" : "=l"(d) : "f"(a));
    return d;
}
__device__ __forceinline__ float2 unpack2(unsigned long long v) {
    float2 f;
    asm("mov.b64 {%0, %1}, %2;" : "=f"(f.x), "=f"(f.y) : "l"(v));
    return f;
}

// ---------------- cp.async helpers ----------------
__device__ __forceinline__ void cpa16(unsigned dst, const void* src, bool pred) {
    int sz = pred ? 16 : 0;
    asm volatile("cp.async.ca.shared.global [%0], [%1], 16, %2;\n"
                 :: "r"(dst), "l"(src), "r"(sz));
}
__device__ __forceinline__ void cpa_commit() { asm volatile("cp.async.commit_group;\n"); }
__device__ __forceinline__ void cpa_wait1()  { asm volatile("cp.async.wait_group 1;\n"); }
__device__ __forceinline__ void cpa_wait0()  { asm volatile("cp.async.wait_group 0;\n"); }

// ---------------- CSR row_ptr from sorted adj_row ----------------
__global__ void build_rowptr_kernel(const int* __restrict__ arow) {
    int r = blockIdx.x * blockDim.x + threadIdx.x;
    if (r > NN) return;
    int lo = 0, hi = EE;
    while (lo < hi) {
        int mid = (lo + hi) >> 1;
        if (arow[mid] < r) lo = mid + 1; else hi = mid;
    }
    g_rowptr[r] = lo;
}

// ---------------- GEMM1: g_s1[N,128] = X[N,256] @ W1[256,128] ----------------
// 128x128 block tile, 256 threads, 8x8 thread tile (4 f32x2 col-pairs),
// BK=16, 2-stage cp.async pipeline.
#define G1_BM 128
#define G1_BK 16
#define G1_AS 20                 // As row stride (floats): 80B, 16B-aligned
#define G1_NT (NFEAT / G1_BK)    // 16 k-tiles
__global__ void __launch_bounds__(256) gemm1_kernel(const float* __restrict__ X,
                                                    const float* __restrict__ W1) {
    __shared__ float As[2][G1_BM * G1_AS];   // 2 x 10240 B
    __shared__ float Bs[2][G1_BK * NHID];    // 2 x 8192 B

    const int tid = threadIdx.x;
    const int tx  = tid & 15;
    const int ty  = tid >> 4;
    const int row0 = blockIdx.x * G1_BM;

    // per-thread prefetch coordinates
    const int a_r  = tid >> 1;               // 2 float4 per 16-float row -> 512 float4, 2/thread
    const int a_c4 = (tid & 1) * 8;          // wait: 16 floats = 4 float4 per row... recompute below
    (void)a_r; (void)a_c4;

    unsigned long long acc[8][4];
#pragma unroll
    for (int i = 0; i < 8; i++)
#pragma unroll
        for (int j = 0; j < 4; j++) acc[i][j] = 0ull;

    unsigned asb = (unsigned)__cvta_generic_to_shared(&As[0][0]);
    unsigned bsb = (unsigned)__cvta_generic_to_shared(&Bs[0][0]);

    // prefetch lambda (macro-style): X tile 128x16 = 512 float4 (2/thread),
    // W1 tile 16x128 = 512 float4 (2/thread)
#define G1_PREFETCH(stage, k0)                                                     \
    do {                                                                           \
        _Pragma("unroll")                                                          \
        for (int j = 0; j < 2; j++) {                                              \
            int fi = j * 256 + tid;          /* [0,512) */                         \
            int r  = fi >> 2;                /* 4 float4 per 16-float row */       \
            int c4 = (fi & 3) * 4;                                                 \
            int grow = row0 + r;                                                   \
            unsigned dst = asb + (stage) * (G1_BM * G1_AS * 4) + (r * G1_AS + c4) * 4; \
            cpa16(dst, &X[(size_t)grow * NFEAT + (k0) + c4], grow < NN);           \
        }                                                                          \
        _Pragma("unroll")                                                          \
        for (int j = 0; j < 2; j++) {                                              \
            int fi = j * 256 + tid;                                                \
            int r  = fi >> 5;                /* 32 float4 per 128-float row */     \
            int c  = (fi & 31) * 4;                                                \
            unsigned dst = bsb + (stage) * (G1_BK * NHID * 4) + (r * NHID + c) * 4;\
            cpa16(dst, &W1[(size_t)((k0) + r) * NHID + c], true);                  \
        }                                                                          \
        cpa_commit();                                                              \
    } while (0)

    G1_PREFETCH(0, 0);

    for (int t = 0; t < G1_NT; t++) {
        if (t + 1 < G1_NT) {
            G1_PREFETCH((t + 1) & 1, (t + 1) * G1_BK);
            cpa_wait1();
        } else {
            cpa_wait0();
        }
        __syncthreads();

        const int st = t & 1;
#pragma unroll
        for (int kk = 0; kk < G1_BK; kk++) {
            unsigned long long ad[8];
#pragma unroll
            for (int i = 0; i < 8; i++)
                ad[i] = dup2(As[st][(ty * 8 + i) * G1_AS + kk]);
            unsigned long long bp[4];
#pragma unroll
            for (int j = 0; j < 4; j++)
                bp[j] = *(const unsigned long long*)&Bs[st][kk * NHID + 2 * tx + 32 * j];
#pragma unroll
            for (int i = 0; i < 8; i++)
#pragma unroll
                for (int j = 0; j < 4; j++)
                    acc[i][j] = ffma2(ad[i], bp[j], acc[i][j]);
        }
        __syncthreads();
    }

#pragma unroll
    for (int i = 0; i < 8; i++) {
        int grow = row0 + ty * 8 + i;
        if (grow < NN) {
#pragma unroll
            for (int j = 0; j < 4; j++) {
                float2 v = unpack2(acc[i][j]);
                *(float2*)&g_s1[(size_t)grow * NHID + 2 * tx + 32 * j] = v;
            }
        }
    }
#undef G1_PREFETCH
}

// ---------------- Fused layer1: h = relu(A@s1 + b1);  s2 = h @ W2 ----------------
// Warp per row. Gather phase as before; then the warp computes its own
// 128x40 row-GEMM against W2 staged in smem. g_h never materializes.
#define FB_WARPS 16
__global__ void __launch_bounds__(FB_WARPS * 32) layer1_fused_kernel(
        const int* __restrict__ acol, const float* __restrict__ aval,
        const float* __restrict__ b1, const float* __restrict__ W2) {
    __shared__ float2 Wint[NHID * 20];          // (W2[d][2c], W2[d][2c+1])  20 KB
    __shared__ float  Hs[FB_WARPS][NHID];       // one h row per warp         8 KB

    const int tid  = threadIdx.x;
    const int wid  = tid >> 5;
    const int lane = tid & 31;

    for (int j = tid; j < NHID * 20; j += FB_WARPS * 32) {
        int d = j / 20, c2 = j % 20;
        Wint[j] = *(const float2*)&W2[d * NCLASS + 2 * c2];
    }
    __syncthreads();

    int w = blockIdx.x * FB_WARPS + wid;
    if (w >= NN) return;

    int s = g_rowptr[w];
    int e = g_rowptr[w + 1];

    const float4* S1v = (const float4*)g_s1;
    float4 acc = make_float4(0.f, 0.f, 0.f, 0.f);

    int i = s;
    for (; i + 1 < e; i += 2) {
        int   c0 = __ldcs(&acol[i]);
        int   c1 = __ldcs(&acol[i + 1]);
        float v0 = __ldcs(&aval[i]);
        float v1 = __ldcs(&aval[i + 1]);
        float4 d0 = __ldcg(&S1v[(size_t)c0 * 32 + lane]);
        float4 d1 = __ldcg(&S1v[(size_t)c1 * 32 + lane]);
        acc.x += v0 * d0.x + v1 * d1.x;
        acc.y += v0 * d0.y + v1 * d1.y;
        acc.z += v0 * d0.z + v1 * d1.z;
        acc.w += v0 * d0.w + v1 * d1.w;
    }
    if (i < e) {
        int   c0 = __ldcs(&acol[i]);
        float v0 = __ldcs(&aval[i]);
        float4 d0 = __ldcg(&S1v[(size_t)c0 * 32 + lane]);
        acc.x += v0 * d0.x; acc.y += v0 * d0.y;
        acc.z += v0 * d0.z; acc.w += v0 * d0.w;
    }

    float4 b = ((const float4*)b1)[lane];
    acc.x = fmaxf(acc.x + b.x, 0.f);
    acc.y = fmaxf(acc.y + b.y, 0.f);
    acc.z = fmaxf(acc.z + b.z, 0.f);
    acc.w = fmaxf(acc.w + b.w, 0.f);

    // stage h row in smem, then row-local GEMM: s2[2l,2l+1] on lanes 0..19
    *(float4*)&Hs[wid][4 * lane] = acc;
    __syncwarp();

    if (lane < 20) {
        const float* hrow = Hs[wid];
        unsigned long long a0 = 0ull, a1 = 0ull, a2 = 0ull, a3 = 0ull;
#pragma unroll
        for (int d = 0; d < NHID; d += 4) {
            float4 hv = *(const float4*)&hrow[d];
            a0 = ffma2(dup2(hv.x), *(const unsigned long long*)&Wint[(d + 0) * 20 + lane], a0);
            a1 = ffma2(dup2(hv.y), *(const unsigned long long*)&Wint[(d + 1) * 20 + lane], a1);
            a2 = ffma2(dup2(hv.z), *(const unsigned long long*)&Wint[(d + 2) * 20 + lane], a2);
            a3 = ffma2(dup2(hv.w), *(const unsigned long long*)&Wint[(d + 3) * 20 + lane], a3);
        }
        float2 p0 = unpack2(a0), p1 = unpack2(a1), p2 = unpack2(a2), p3 = unpack2(a3);
        float2 s2v;
        s2v.x = (p0.x + p1.x) + (p2.x + p3.x);
        s2v.y = (p0.y + p1.y) + (p2.y + p3.y);
        *(float2*)&g_s2[(size_t)w * NCLASS + 2 * lane] = s2v;
    }
}

// ---------------- SpMM2 + bias + log_softmax ----------------
__global__ void spmm2_lsm_kernel(const int* __restrict__ acol, const float* __restrict__ aval,
                                 const float* __restrict__ b2, float* __restrict__ out) {
    int warp = (blockIdx.x * blockDim.x + threadIdx.x) >> 5;
    int lane = threadIdx.x & 31;
    if (warp >= NN) return;

    int s = g_rowptr[warp];
    int e = g_rowptr[warp + 1];
    bool active = lane < 20;

    const float2* S2v = (const float2*)g_s2;
    float2 acc = make_float2(0.f, 0.f);

    int i = s;
    for (; i + 1 < e; i += 2) {
        int   c0 = __ldcs(&acol[i]);
        int   c1 = __ldcs(&acol[i + 1]);
        float v0 = __ldcs(&aval[i]);
        float v1 = __ldcs(&aval[i + 1]);
        if (active) {
            float2 d0 = __ldcg(&S2v[(size_t)c0 * 20 + lane]);
            float2 d1 = __ldcg(&S2v[(size_t)c1 * 20 + lane]);
            acc.x += v0 * d0.x + v1 * d1.x;
            acc.y += v0 * d0.y + v1 * d1.y;
        }
    }
    if (i < e) {
        int   c0 = __ldcs(&acol[i]);
        float v0 = __ldcs(&aval[i]);
        if (active) {
            float2 d0 = __ldcg(&S2v[(size_t)c0 * 20 + lane]);
            acc.x += v0 * d0.x;
            acc.y += v0 * d0.y;
        }
    }

    if (active) {
        acc.x += __ldg(&b2[2 * lane]);
        acc.y += __ldg(&b2[2 * lane + 1]);
    }

    float m = active ? fmaxf(acc.x, acc.y) : -INFINITY;
#pragma unroll
    for (int off = 16; off > 0; off >>= 1)
        m = fmaxf(m, __shfl_xor_sync(0xFFFFFFFFu, m, off));

    float se = active ? (expf(acc.x - m) + expf(acc.y - m)) : 0.f;
#pragma unroll
    for (int off = 16; off > 0; off >>= 1)
        se += __shfl_xor_sync(0xFFFFFFFFu, se, off);

    float lse = m + logf(se);
    if (active) {
        out[(size_t)warp * NCLASS + 2 * lane]     = acc.x - lse;
        out[(size_t)warp * NCLASS + 2 * lane + 1] = acc.y - lse;
    }
}

// ---------------- launch ----------------
extern "C" void kernel_launch(void* const* d_in, const int* in_sizes, int n_in,
                              void* d_out, int out_size) {
    const float* x    = (const float*)d_in[0];
    const int*   arow = (const int*)  d_in[1];
    const int*   acol = (const int*)  d_in[2];
    const float* aval = (const float*)d_in[3];
    // d_in[4] = i (unused scalar)
    const float* W1 = (const float*)d_in[5];
    const float* b1 = (const float*)d_in[6];
    const float* W2 = (const float*)d_in[7];
    const float* b2 = (const float*)d_in[8];
    float* out = (float*)d_out;

    build_rowptr_kernel<<<(NN + 1 + 255) / 256, 256>>>(arow);
    gemm1_kernel<<<(NN + G1_BM - 1) / G1_BM, 256>>>(x, W1);
    layer1_fused_kernel<<<(NN + FB_WARPS - 1) / FB_WARPS, FB_WARPS * 32>>>(acol, aval, b1, W2);
    spmm2_lsm_kernel<<<(NN * 32 + 255) / 256, 256>>>(acol, aval, b2, out);
}

// round 4
// speedup vs baseline: 1.1226x; 1.1226x over previous
#include <cuda_runtime.h>
#include <math.h>

#define NN    100000
#define EE    3200000
#define NFEAT 256
#define NHID  128
#define NCLASS 40

// ---------------- scratch ----------------
__device__ __align__(16) float g_s1[NN * NHID];     // x @ W1 (51.2 MB)
__device__ __align__(16) float g_h [NN * NHID];     // relu(A@s1 + b1) (51.2 MB)
__device__ __align__(16) float g_s2[NN * NCLASS];   // h @ W2 (16 MB)
__device__ int g_rowptr[NN + 1];

// ---------------- f32x2 packed helpers ----------------
__device__ __forceinline__ unsigned long long ffma2(unsigned long long a,
                                                    unsigned long long b,
                                                    unsigned long long c) {
    unsigned long long d;
    asm("fma.rn.f32x2 %0, %1, %2, %3;" : "=l"(d) : "l"(a), "l"(b), "l"(c));
    return d;
}
__device__ __forceinline__ unsigned long long dup2(float a) {
    unsigned long long d;
    asm("mov.b64 %0, {%1, %1};" : "=l"(d) : "f"(a));
    return d;
}
__device__ __forceinline__ float2 unpack2(unsigned long long v) {
    float2 f;
    asm("mov.b64 {%0, %1}, %2;" : "=f"(f.x), "=f"(f.y) : "l"(v));
    return f;
}
__device__ __forceinline__ unsigned long long ldg64cg(const void* p) {
    unsigned long long v;
    asm volatile("ld.global.cg.b64 %0, [%1];" : "=l"(v) : "l"(p));
    return v;
}
__device__ __forceinline__ void ldg128cg(const void* p, unsigned long long& a,
                                         unsigned long long& b) {
    asm volatile("ld.global.cg.v2.u64 {%0, %1}, [%2];" : "=l"(a), "=l"(b) : "l"(p));
}

// ---------------- cp.async helpers ----------------
__device__ __forceinline__ void cpa16(unsigned dst, const void* src, bool pred) {
    int sz = pred ? 16 : 0;
    asm volatile("cp.async.ca.shared.global [%0], [%1], 16, %2;\n"
                 :: "r"(dst), "l"(src), "r"(sz));
}
__device__ __forceinline__ void cpa_commit() { asm volatile("cp.async.commit_group;\n"); }
__device__ __forceinline__ void cpa_wait1()  { asm volatile("cp.async.wait_group 1;\n"); }
__device__ __forceinline__ void cpa_wait0()  { asm volatile("cp.async.wait_group 0;\n"); }

// ---------------- CSR row_ptr ----------------
__global__ void build_rowptr_kernel(const int* __restrict__ arow) {
    int r = blockIdx.x * blockDim.x + threadIdx.x;
    if (r > NN) return;
    int lo = 0, hi = EE;
    while (lo < hi) {
        int mid = (lo + hi) >> 1;
        if (arow[mid] < r) lo = mid + 1; else hi = mid;
    }
    g_rowptr[r] = lo;
}

// ---------------- GEMM1: g_s1 = X @ W1, 128x128 tile, f32x2, cp.async 2-stage ----------------
#define G1_BM 128
#define G1_BK 16
#define G1_AS 20
#define G1_NT (NFEAT / G1_BK)
__global__ void __launch_bounds__(256) gemm1_kernel(const float* __restrict__ X,
                                                    const float* __restrict__ W1) {
    __shared__ float As[2][G1_BM * G1_AS];
    __shared__ float Bs[2][G1_BK * NHID];

    const int tid = threadIdx.x;
    const int tx  = tid & 15;
    const int ty  = tid >> 4;
    const int row0 = blockIdx.x * G1_BM;

    unsigned long long acc[8][4];
#pragma unroll
    for (int i = 0; i < 8; i++)
#pragma unroll
        for (int j = 0; j < 4; j++) acc[i][j] = 0ull;

    unsigned asb = (unsigned)__cvta_generic_to_shared(&As[0][0]);
    unsigned bsb = (unsigned)__cvta_generic_to_shared(&Bs[0][0]);

#define G1_PREFETCH(stage, k0)                                                     \
    do {                                                                           \
        _Pragma("unroll")                                                          \
        for (int j = 0; j < 2; j++) {                                              \
            int fi = j * 256 + tid;                                                \
            int r  = fi >> 2;                                                      \
            int c4 = (fi & 3) * 4;                                                 \
            int grow = row0 + r;                                                   \
            unsigned dst = asb + (stage) * (G1_BM * G1_AS * 4) + (r * G1_AS + c4) * 4; \
            cpa16(dst, &X[(size_t)grow * NFEAT + (k0) + c4], grow < NN);           \
        }                                                                          \
        _Pragma("unroll")                                                          \
        for (int j = 0; j < 2; j++) {                                              \
            int fi = j * 256 + tid;                                                \
            int r  = fi >> 5;                                                      \
            int c  = (fi & 31) * 4;                                                \
            unsigned dst = bsb + (stage) * (G1_BK * NHID * 4) + (r * NHID + c) * 4;\
            cpa16(dst, &W1[(size_t)((k0) + r) * NHID + c], true);                  \
        }                                                                          \
        cpa_commit();                                                              \
    } while (0)

    G1_PREFETCH(0, 0);

    for (int t = 0; t < G1_NT; t++) {
        if (t + 1 < G1_NT) {
            G1_PREFETCH((t + 1) & 1, (t + 1) * G1_BK);
            cpa_wait1();
        } else {
            cpa_wait0();
        }
        __syncthreads();

        const int st = t & 1;
#pragma unroll
        for (int kk = 0; kk < G1_BK; kk++) {
            unsigned long long ad[8];
#pragma unroll
            for (int i = 0; i < 8; i++)
                ad[i] = dup2(As[st][(ty * 8 + i) * G1_AS + kk]);
            unsigned long long bp[4];
#pragma unroll
            for (int j = 0; j < 4; j++)
                bp[j] = *(const unsigned long long*)&Bs[st][kk * NHID + 2 * tx + 32 * j];
#pragma unroll
            for (int i = 0; i < 8; i++)
#pragma unroll
                for (int j = 0; j < 4; j++)
                    acc[i][j] = ffma2(ad[i], bp[j], acc[i][j]);
        }
        __syncthreads();
    }

#pragma unroll
    for (int i = 0; i < 8; i++) {
        int grow = row0 + ty * 8 + i;
        if (grow < NN) {
#pragma unroll
            for (int j = 0; j < 4; j++) {
                float2 v = unpack2(acc[i][j]);
                *(float2*)&g_s1[(size_t)grow * NHID + 2 * tx + 32 * j] = v;
            }
        }
    }
#undef G1_PREFETCH
}

// ---------------- SpMM1 + bias + ReLU (warp/row, f32x2 accum, 16B gathers) ----------------
__global__ void spmm1_kernel(const int* __restrict__ acol, const float* __restrict__ aval,
                             const float* __restrict__ b1) {
    int warp = (blockIdx.x * blockDim.x + threadIdx.x) >> 5;
    int lane = threadIdx.x & 31;
    if (warp >= NN) return;

    int s = g_rowptr[warp];
    int e = g_rowptr[warp + 1];

    const char* S1b = (const char*)g_s1 + (size_t)lane * 16;   // lane's 16B slice
    unsigned long long a01 = 0ull, a23 = 0ull;

    int i = s;
    if ((i & 1) && i < e) {                 // peel to 2-alignment
        int   c = __ldcs(&acol[i]);
        float v = __ldcs(&aval[i]);
        unsigned long long d0, d1;
        ldg128cg(S1b + (size_t)c * 512, d0, d1);
        unsigned long long vv = dup2(v);
        a01 = ffma2(vv, d0, a01);
        a23 = ffma2(vv, d1, a23);
        i++;
    }
    for (; i + 1 < e; i += 2) {
        int2   c2 = __ldcs((const int2*)&acol[i]);
        float2 v2 = __ldcs((const float2*)&aval[i]);
        unsigned long long d0, d1, e0, e1;
        ldg128cg(S1b + (size_t)c2.x * 512, d0, d1);
        ldg128cg(S1b + (size_t)c2.y * 512, e0, e1);
        unsigned long long vx = dup2(v2.x), vy = dup2(v2.y);
        a01 = ffma2(vx, d0, a01);
        a23 = ffma2(vx, d1, a23);
        a01 = ffma2(vy, e0, a01);
        a23 = ffma2(vy, e1, a23);
    }
    if (i < e) {
        int   c = __ldcs(&acol[i]);
        float v = __ldcs(&aval[i]);
        unsigned long long d0, d1;
        ldg128cg(S1b + (size_t)c * 512, d0, d1);
        unsigned long long vv = dup2(v);
        a01 = ffma2(vv, d0, a01);
        a23 = ffma2(vv, d1, a23);
    }

    float2 p01 = unpack2(a01), p23 = unpack2(a23);
    float4 b = ((const float4*)b1)[lane];
    float4 r;
    r.x = fmaxf(p01.x + b.x, 0.f);
    r.y = fmaxf(p01.y + b.y, 0.f);
    r.z = fmaxf(p23.x + b.z, 0.f);
    r.w = fmaxf(p23.y + b.w, 0.f);
    ((float4*)g_h)[(size_t)warp * 32 + lane] = r;
}

// ---------------- GEMM2: s2 = h @ W2, BM=128, 512 thr, 2x5 thread tile ----------------
#define G2_BM 128
#define G2_BK 32
#define G2_HS 33
__global__ void __launch_bounds__(512) gemm2_kernel(const float* __restrict__ W2) {
    __shared__ float Ws[NHID * NCLASS];        // 20 KB
    __shared__ float Hs[G2_BM * G2_HS];        // 16.9 KB

    const int tid  = threadIdx.x;
    const int rgrp = tid >> 3;                 // 0..63
    const int cg   = tid & 7;                  // cols cg*5..+4
    const int row0 = blockIdx.x * G2_BM;

    for (int j = tid; j < NHID * NCLASS; j += 512) Ws[j] = W2[j];

    float acc[2][5];
#pragma unroll
    for (int i = 0; i < 2; i++)
#pragma unroll
        for (int c = 0; c < 5; c++) acc[i][c] = 0.f;

    for (int k0 = 0; k0 < NHID; k0 += G2_BK) {
        // 128 rows x 32 cols = 1024 float4, 2 per thread
#pragma unroll
        for (int j = 0; j < 2; j++) {
            int fi = j * 512 + tid;
            int r  = fi >> 3;
            int c4 = (fi & 7) * 4;
            int grow = row0 + r;
            float4 v = make_float4(0.f, 0.f, 0.f, 0.f);
            if (grow < NN) v = *(const float4*)&g_h[(size_t)grow * NHID + k0 + c4];
            Hs[r * G2_HS + c4 + 0] = v.x;
            Hs[r * G2_HS + c4 + 1] = v.y;
            Hs[r * G2_HS + c4 + 2] = v.z;
            Hs[r * G2_HS + c4 + 3] = v.w;
        }
        __syncthreads();

#pragma unroll
        for (int kk = 0; kk < G2_BK; kk++) {
            float ws[5];
#pragma unroll
            for (int c = 0; c < 5; c++) ws[c] = Ws[(k0 + kk) * NCLASS + cg * 5 + c];
#pragma unroll
            for (int i = 0; i < 2; i++) {
                float hv = Hs[(rgrp + 64 * i) * G2_HS + kk];
#pragma unroll
                for (int c = 0; c < 5; c++) acc[i][c] += hv * ws[c];
            }
        }
        __syncthreads();
    }

#pragma unroll
    for (int i = 0; i < 2; i++) {
        int grow = row0 + rgrp + 64 * i;
        if (grow < NN) {
#pragma unroll
            for (int c = 0; c < 5; c++)
                g_s2[(size_t)grow * NCLASS + cg * 5 + c] = acc[i][c];
        }
    }
}

// ---------------- SpMM2 + bias + log_softmax (f32x2, 4-edge unroll) ----------------
__global__ void spmm2_lsm_kernel(const int* __restrict__ acol, const float* __restrict__ aval,
                                 const float* __restrict__ b2, float* __restrict__ out) {
    int warp = (blockIdx.x * blockDim.x + threadIdx.x) >> 5;
    int lane = threadIdx.x & 31;
    if (warp >= NN) return;

    int s = g_rowptr[warp];
    int e = g_rowptr[warp + 1];
    bool active = lane < 20;

    const char* S2b = (const char*)g_s2 + (size_t)lane * 8;
    unsigned long long acc = 0ull;

    int i = s;
    while (i < e && (i & 3)) {              // peel to 4-alignment
        int   c = __ldcs(&acol[i]);
        float v = __ldcs(&aval[i]);
        if (active) acc = ffma2(dup2(v), ldg64cg(S2b + (size_t)c * 160), acc);
        i++;
    }
    for (; i + 3 < e; i += 4) {
        int4   c4 = __ldcs((const int4*)&acol[i]);
        float4 v4 = __ldcs((const float4*)&aval[i]);
        if (active) {
            unsigned long long d0 = ldg64cg(S2b + (size_t)c4.x * 160);
            unsigned long long d1 = ldg64cg(S2b + (size_t)c4.y * 160);
            unsigned long long d2 = ldg64cg(S2b + (size_t)c4.z * 160);
            unsigned long long d3 = ldg64cg(S2b + (size_t)c4.w * 160);
            acc = ffma2(dup2(v4.x), d0, acc);
            acc = ffma2(dup2(v4.y), d1, acc);
            acc = ffma2(dup2(v4.z), d2, acc);
            acc = ffma2(dup2(v4.w), d3, acc);
        }
    }
    for (; i < e; i++) {
        int   c = __ldcs(&acol[i]);
        float v = __ldcs(&aval[i]);
        if (active) acc = ffma2(dup2(v), ldg64cg(S2b + (size_t)c * 160), acc);
    }

    float2 av = unpack2(acc);
    if (active) {
        float2 bb = *(const float2*)&b2[2 * lane];
        av.x += bb.x;
        av.y += bb.y;
    }

    float m = active ? fmaxf(av.x, av.y) : -INFINITY;
#pragma unroll
    for (int off = 16; off > 0; off >>= 1)
        m = fmaxf(m, __shfl_xor_sync(0xFFFFFFFFu, m, off));

    float se = active ? (expf(av.x - m) + expf(av.y - m)) : 0.f;
#pragma unroll
    for (int off = 16; off > 0; off >>= 1)
        se += __shfl_xor_sync(0xFFFFFFFFu, se, off);

    float lse = m + logf(se);
    if (active) {
        out[(size_t)warp * NCLASS + 2 * lane]     = av.x - lse;
        out[(size_t)warp * NCLASS + 2 * lane + 1] = av.y - lse;
    }
}

// ---------------- launch ----------------
extern "C" void kernel_launch(void* const* d_in, const int* in_sizes, int n_in,
                              void* d_out, int out_size) {
    const float* x    = (const float*)d_in[0];
    const int*   arow = (const int*)  d_in[1];
    const int*   acol = (const int*)  d_in[2];
    const float* aval = (const float*)d_in[3];
    // d_in[4] = i (unused)
    const float* W1 = (const float*)d_in[5];
    const float* b1 = (const float*)d_in[6];
    const float* W2 = (const float*)d_in[7];
    const float* b2 = (const float*)d_in[8];
    float* out = (float*)d_out;

    build_rowptr_kernel<<<(NN + 1 + 255) / 256, 256>>>(arow);
    gemm1_kernel<<<(NN + G1_BM - 1) / G1_BM, 256>>>(x, W1);
    spmm1_kernel<<<(NN * 32 + 255) / 256, 256>>>(acol, aval, b1);
    gemm2_kernel<<<(NN + G2_BM - 1) / G2_BM, 512>>>(W2);
    spmm2_lsm_kernel<<<(NN * 32 + 255) / 256, 256>>>(acol, aval, b2, out);
}

// round 6
// speedup vs baseline: 1.1775x; 1.0490x over previous
#include <cuda_runtime.h>
#include <math.h>

#define NN    100000
#define EE    3200000
#define NFEAT 256
#define NHID  128
#define NCLASS 40

// ---------------- scratch ----------------
__device__ __align__(16) float g_s1[NN * NHID];     // x @ W1 (51.2 MB)
__device__ __align__(16) float g_h [NN * NHID];     // relu(A@s1 + b1) (51.2 MB)
__device__ __align__(16) float g_s2[NN * NCLASS];   // h @ W2 (16 MB)
__device__ int g_rowptr[NN + 1];

// ---------------- f32x2 packed helpers ----------------
__device__ __forceinline__ unsigned long long ffma2(unsigned long long a,
                                                    unsigned long long b,
                                                    unsigned long long c) {
    unsigned long long d;
    asm("fma.rn.f32x2 %0, %1, %2, %3;" : "=l"(d) : "l"(a), "l"(b), "l"(c));
    return d;
}
__device__ __forceinline__ unsigned long long dup2(float a) {
    unsigned long long d;
    asm("mov.b64 %0, {%1, %1};" : "=l"(d) : "f"(a));
    return d;
}
__device__ __forceinline__ float2 unpack2(unsigned long long v) {
    float2 f;
    asm("mov.b64 {%0, %1}, %2;" : "=f"(f.x), "=f"(f.y) : "l"(v));
    return f;
}
__device__ __forceinline__ unsigned long long ldg64cg(const void* p) {
    unsigned long long v;
    asm volatile("ld.global.cg.b64 %0, [%1];" : "=l"(v) : "l"(p));
    return v;
}
__device__ __forceinline__ void ldg128cg(const void* p, unsigned long long& a,
                                         unsigned long long& b) {
    asm volatile("ld.global.cg.v2.u64 {%0, %1}, [%2];" : "=l"(a), "=l"(b) : "l"(p));
}

// ---------------- cp.async helpers ----------------
__device__ __forceinline__ void cpa16(unsigned dst, const void* src, bool pred) {
    int sz = pred ? 16 : 0;
    asm volatile("cp.async.ca.shared.global [%0], [%1], 16, %2;\n"
                 :: "r"(dst), "l"(src), "r"(sz));
}
__device__ __forceinline__ void cpa_commit() { asm volatile("cp.async.commit_group;\n"); }
__device__ __forceinline__ void cpa_wait1()  { asm volatile("cp.async.wait_group 1;\n"); }
__device__ __forceinline__ void cpa_wait0()  { asm volatile("cp.async.wait_group 0;\n"); }

// ---------------- CSR row_ptr ----------------
__global__ void build_rowptr_kernel(const int* __restrict__ arow) {
    int r = blockIdx.x * blockDim.x + threadIdx.x;
    if (r > NN) return;
    int lo = 0, hi = EE;
    while (lo < hi) {
        int mid = (lo + hi) >> 1;
        if (arow[mid] < r) lo = mid + 1; else hi = mid;
    }
    g_rowptr[r] = lo;
}

// ---------------- GEMM1: g_s1 = X @ W1, 128x128 tile, f32x2, cp.async 2-stage ----------------
#define G1_BM 128
#define G1_BK 16
#define G1_AS 20
#define G1_NT (NFEAT / G1_BK)
__global__ void __launch_bounds__(256) gemm1_kernel(const float* __restrict__ X,
                                                    const float* __restrict__ W1) {
    __shared__ float As[2][G1_BM * G1_AS];
    __shared__ float Bs[2][G1_BK * NHID];

    const int tid = threadIdx.x;
    const int tx  = tid & 15;
    const int ty  = tid >> 4;
    const int row0 = blockIdx.x * G1_BM;

    unsigned long long acc[8][4];
#pragma unroll
    for (int i = 0; i < 8; i++)
#pragma unroll
        for (int j = 0; j < 4; j++) acc[i][j] = 0ull;

    unsigned asb = (unsigned)__cvta_generic_to_shared(&As[0][0]);
    unsigned bsb = (unsigned)__cvta_generic_to_shared(&Bs[0][0]);

#define G1_PREFETCH(stage, k0)                                                     \
    do {                                                                           \
        _Pragma("unroll")                                                          \
        for (int j = 0; j < 2; j++) {                                              \
            int fi = j * 256 + tid;                                                \
            int r  = fi >> 2;                                                      \
            int c4 = (fi & 3) * 4;                                                 \
            int grow = row0 + r;                                                   \
            unsigned dst = asb + (stage) * (G1_BM * G1_AS * 4) + (r * G1_AS + c4) * 4; \
            cpa16(dst, &X[(size_t)grow * NFEAT + (k0) + c4], grow < NN);           \
        }                                                                          \
        _Pragma("unroll")                                                          \
        for (int j = 0; j < 2; j++) {                                              \
            int fi = j * 256 + tid;                                                \
            int r  = fi >> 5;                                                      \
            int c  = (fi & 31) * 4;                                                \
            unsigned dst = bsb + (stage) * (G1_BK * NHID * 4) + (r * NHID + c) * 4;\
            cpa16(dst, &W1[(size_t)((k0) + r) * NHID + c], true);                  \
        }                                                                          \
        cpa_commit();                                                              \
    } while (0)

    G1_PREFETCH(0, 0);

    for (int t = 0; t < G1_NT; t++) {
        if (t + 1 < G1_NT) {
            G1_PREFETCH((t + 1) & 1, (t + 1) * G1_BK);
            cpa_wait1();
        } else {
            cpa_wait0();
        }
        __syncthreads();

        const int st = t & 1;
#pragma unroll
        for (int kk = 0; kk < G1_BK; kk++) {
            unsigned long long ad[8];
#pragma unroll
            for (int i = 0; i < 8; i++)
                ad[i] = dup2(As[st][(ty * 8 + i) * G1_AS + kk]);
            unsigned long long bp[4];
#pragma unroll
            for (int j = 0; j < 4; j++)
                bp[j] = *(const unsigned long long*)&Bs[st][kk * NHID + 2 * tx + 32 * j];
#pragma unroll
            for (int i = 0; i < 8; i++)
#pragma unroll
                for (int j = 0; j < 4; j++)
                    acc[i][j] = ffma2(ad[i], bp[j], acc[i][j]);
        }
        __syncthreads();
    }

#pragma unroll
    for (int i = 0; i < 8; i++) {
        int grow = row0 + ty * 8 + i;
        if (grow < NN) {
#pragma unroll
            for (int j = 0; j < 4; j++) {
                float2 v = unpack2(acc[i][j]);
                *(float2*)&g_s1[(size_t)grow * NHID + 2 * tx + 32 * j] = v;
            }
        }
    }
#undef G1_PREFETCH
}

// ---------------- SpMM1 + bias + ReLU (warp/row, f32x2 accum, 16B gathers) ----------------
__global__ void spmm1_kernel(const int* __restrict__ acol, const float* __restrict__ aval,
                             const float* __restrict__ b1) {
    int warp = (blockIdx.x * blockDim.x + threadIdx.x) >> 5;
    int lane = threadIdx.x & 31;
    if (warp >= NN) return;

    int s = g_rowptr[warp];
    int e = g_rowptr[warp + 1];

    const char* S1b = (const char*)g_s1 + (size_t)lane * 16;
    unsigned long long a01 = 0ull, a23 = 0ull;

    int i = s;
    if ((i & 1) && i < e) {
        int   c = __ldcs(&acol[i]);
        float v = __ldcs(&aval[i]);
        unsigned long long d0, d1;
        ldg128cg(S1b + (size_t)c * 512, d0, d1);
        unsigned long long vv = dup2(v);
        a01 = ffma2(vv, d0, a01);
        a23 = ffma2(vv, d1, a23);
        i++;
    }
    for (; i + 1 < e; i += 2) {
        int2   c2 = __ldcs((const int2*)&acol[i]);
        float2 v2 = __ldcs((const float2*)&aval[i]);
        unsigned long long d0, d1, e0, e1;
        ldg128cg(S1b + (size_t)c2.x * 512, d0, d1);
        ldg128cg(S1b + (size_t)c2.y * 512, e0, e1);
        unsigned long long vx = dup2(v2.x), vy = dup2(v2.y);
        a01 = ffma2(vx, d0, a01);
        a23 = ffma2(vx, d1, a23);
        a01 = ffma2(vy, e0, a01);
        a23 = ffma2(vy, e1, a23);
    }
    if (i < e) {
        int   c = __ldcs(&acol[i]);
        float v = __ldcs(&aval[i]);
        unsigned long long d0, d1;
        ldg128cg(S1b + (size_t)c * 512, d0, d1);
        unsigned long long vv = dup2(v);
        a01 = ffma2(vv, d0, a01);
        a23 = ffma2(vv, d1, a23);
    }

    float2 p01 = unpack2(a01), p23 = unpack2(a23);
    float4 b = ((const float4*)b1)[lane];
    float4 r;
    r.x = fmaxf(p01.x + b.x, 0.f);
    r.y = fmaxf(p01.y + b.y, 0.f);
    r.z = fmaxf(p23.x + b.z, 0.f);
    r.w = fmaxf(p23.y + b.w, 0.f);
    ((float4*)g_h)[(size_t)warp * 32 + lane] = r;
}

// ---------------- GEMM2: s2 = h @ W2 ----------------
// BM=256, 256 threads, thread tile 4 rows (stride 64) x 5 col-pairs (f32x2).
// W2 pre-paired in smem; Hs double-buffered via cp.async, BK=8, row stride 12
// floats (48B = 16B-multiple -> cp.async-legal; rg*12 mod 32 conflict-free).
#define G2_BM 256
#define G2_BK 8
#define G2_HS 12
#define G2_NT (NHID / G2_BK)     // 16
__global__ void __launch_bounds__(256) gemm2_kernel(const float* __restrict__ W2) {
    __shared__ float  Hs[2][G2_BM * G2_HS];   // 2 x 12288 B
    __shared__ float2 Wp[NHID * 20];          // 20480 B (pair-major)

    const int tid = threadIdx.x;
    const int pg  = tid & 3;                  // pairs pg*5 .. pg*5+4
    const int rg  = tid >> 2;                 // rows rg + 64*i, i=0..3
    const int row0 = blockIdx.x * G2_BM;

    for (int j = tid; j < NHID * 20; j += 256) {
        int k = j / 20, p = j % 20;
        Wp[j] = *(const float2*)&W2[k * NCLASS + 2 * p];
    }

    unsigned hsb = (unsigned)__cvta_generic_to_shared(&Hs[0][0]);

    // per k-tile: 256 rows x 8 floats = 512 float4, 2 per thread
#define G2_PREFETCH(stage, k0)                                                     \
    do {                                                                           \
        _Pragma("unroll")                                                          \
        for (int j = 0; j < 2; j++) {                                              \
            int fi = j * 256 + tid;          /* [0,512) float4 */                  \
            int r  = fi >> 1;                /* 2 float4 per 8-float row */        \
            int c4 = (fi & 1) * 4;                                                 \
            int grow = row0 + r;                                                   \
            unsigned dst = hsb + (stage) * (G2_BM * G2_HS * 4) + (r * G2_HS + c4) * 4; \
            cpa16(dst, &g_h[(size_t)grow * NHID + (k0) + c4], grow < NN);          \
        }                                                                          \
        cpa_commit();                                                              \
    } while (0)

    G2_PREFETCH(0, 0);

    unsigned long long acc[4][5];
#pragma unroll
    for (int i = 0; i < 4; i++)
#pragma unroll
        for (int j = 0; j < 5; j++) acc[i][j] = 0ull;

    for (int t = 0; t < G2_NT; t++) {
        if (t + 1 < G2_NT) {
            G2_PREFETCH((t + 1) & 1, (t + 1) * G2_BK);
            cpa_wait1();
        } else {
            cpa_wait0();
        }
        __syncthreads();

        const int st = t & 1;
        const int kbase = t * G2_BK;
#pragma unroll
        for (int kk = 0; kk < G2_BK; kk++) {
            unsigned long long hd[4];
#pragma unroll
            for (int i = 0; i < 4; i++)
                hd[i] = dup2(Hs[st][(rg + 64 * i) * G2_HS + kk]);
            unsigned long long wv[5];
#pragma unroll
            for (int j = 0; j < 5; j++)
                wv[j] = *(const unsigned long long*)&Wp[(kbase + kk) * 20 + pg * 5 + j];
#pragma unroll
            for (int i = 0; i < 4; i++)
#pragma unroll
                for (int j = 0; j < 5; j++)
                    acc[i][j] = ffma2(hd[i], wv[j], acc[i][j]);
        }
        __syncthreads();
    }

#pragma unroll
    for (int i = 0; i < 4; i++) {
        int grow = row0 + rg + 64 * i;
        if (grow < NN) {
#pragma unroll
            for (int j = 0; j < 5; j++) {
                float2 v = unpack2(acc[i][j]);
                *(float2*)&g_s2[(size_t)grow * NCLASS + 2 * (pg * 5 + j)] = v;
            }
        }
    }
#undef G2_PREFETCH
}

// ---------------- SpMM2 + bias + log_softmax (f32x2, 4-edge unroll) ----------------
__global__ void spmm2_lsm_kernel(const int* __restrict__ acol, const float* __restrict__ aval,
                                 const float* __restrict__ b2, float* __restrict__ out) {
    int warp = (blockIdx.x * blockDim.x + threadIdx.x) >> 5;
    int lane = threadIdx.x & 31;
    if (warp >= NN) return;

    int s = g_rowptr[warp];
    int e = g_rowptr[warp + 1];
    bool active = lane < 20;

    const char* S2b = (const char*)g_s2 + (size_t)lane * 8;
    unsigned long long acc = 0ull;

    int i = s;
    while (i < e && (i & 3)) {
        int   c = __ldcs(&acol[i]);
        float v = __ldcs(&aval[i]);
        if (active) acc = ffma2(dup2(v), ldg64cg(S2b + (size_t)c * 160), acc);
        i++;
    }
    for (; i + 3 < e; i += 4) {
        int4   c4 = __ldcs((const int4*)&acol[i]);
        float4 v4 = __ldcs((const float4*)&aval[i]);
        if (active) {
            unsigned long long d0 = ldg64cg(S2b + (size_t)c4.x * 160);
            unsigned long long d1 = ldg64cg(S2b + (size_t)c4.y * 160);
            unsigned long long d2 = ldg64cg(S2b + (size_t)c4.z * 160);
            unsigned long long d3 = ldg64cg(S2b + (size_t)c4.w * 160);
            acc = ffma2(dup2(v4.x), d0, acc);
            acc = ffma2(dup2(v4.y), d1, acc);
            acc = ffma2(dup2(v4.z), d2, acc);
            acc = ffma2(dup2(v4.w), d3, acc);
        }
    }
    for (; i < e; i++) {
        int   c = __ldcs(&acol[i]);
        float v = __ldcs(&aval[i]);
        if (active) acc = ffma2(dup2(v), ldg64cg(S2b + (size_t)c * 160), acc);
    }

    float2 av = unpack2(acc);
    if (active) {
        float2 bb = *(const float2*)&b2[2 * lane];
        av.x += bb.x;
        av.y += bb.y;
    }

    float m = active ? fmaxf(av.x, av.y) : -INFINITY;
#pragma unroll
    for (int off = 16; off > 0; off >>= 1)
        m = fmaxf(m, __shfl_xor_sync(0xFFFFFFFFu, m, off));

    float se = active ? (expf(av.x - m) + expf(av.y - m)) : 0.f;
#pragma unroll
    for (int off = 16; off > 0; off >>= 1)
        se += __shfl_xor_sync(0xFFFFFFFFu, se, off);

    float lse = m + logf(se);
    if (active) {
        out[(size_t)warp * NCLASS + 2 * lane]     = av.x - lse;
        out[(size_t)warp * NCLASS + 2 * lane + 1] = av.y - lse;
    }
}

// ---------------- launch ----------------
extern "C" void kernel_launch(void* const* d_in, const int* in_sizes, int n_in,
                              void* d_out, int out_size) {
    const float* x    = (const float*)d_in[0];
    const int*   arow = (const int*)  d_in[1];
    const int*   acol = (const int*)  d_in[2];
    const float* aval = (const float*)d_in[3];
    // d_in[4] = i (unused)
    const float* W1 = (const float*)d_in[5];
    const float* b1 = (const float*)d_in[6];
    const float* W2 = (const float*)d_in[7];
    const float* b2 = (const float*)d_in[8];
    float* out = (float*)d_out;

    build_rowptr_kernel<<<(NN + 1 + 255) / 256, 256>>>(arow);
    gemm1_kernel<<<(NN + G1_BM - 1) / G1_BM, 256>>>(x, W1);
    spmm1_kernel<<<(NN * 32 + 255) / 256, 256>>>(acol, aval, b1);
    gemm2_kernel<<<(NN + G2_BM - 1) / G2_BM, 256>>>(W2);
    spmm2_lsm_kernel<<<(NN * 32 + 255) / 256, 256>>>(acol, aval, b2, out);
}